// round 9
// baseline (speedup 1.0000x reference)
#include <cuda_runtime.h>
#include <cstdint>

#define Bq 900
#define Cc 80
#define QC 72000          // Bq*Cc
#define NV4H 9000         // float4s per half row
#define TOPK 300
#define KP 17
#define THRESH 2.5f
#define MAXB 512

#define FT 256            // k1 threads
#define FW 8              // k1 warps
#define WSEG 64           // keys per warp segment
#define CAPH 512          // per-half capacity (FW*WSEG)
#define UNROLL 4

#define MT 512            // k2 threads
#define CAP2 2048         // k2 shared buffer (16KB); fallback hist alias

// out layout (floats): labels[B*300] | boxes[B*300*4] | scores[B*300] | kpts[B*300*17*2]

__device__ unsigned long long g_keys[(size_t)2 * MAXB * CAPH];  // 4MB, rewritten each run
__device__ int g_cnt[2 * MAXB];                                  // rewritten each run

__device__ __forceinline__ unsigned long long make_key(float f, int idx) {
    unsigned int u = __float_as_uint(f);
    u = (u & 0x80000000u) ? ~u : (u | 0x80000000u);   // monotone-increasing map
    return ((unsigned long long)u << 32) | (unsigned int)(~idx); // smaller idx -> larger key
}

__device__ __forceinline__ float max4(float4 v) {
    return fmaxf(fmaxf(v.x, v.y), fmaxf(v.z, v.w));
}

// ---------------- Kernel 1: stream half-row, filter, coalesced dump (NO sort) ----------------
__global__ __launch_bounds__(FT, 8)
void filter_k(const float* __restrict__ logits) {
    __shared__ unsigned long long seg[CAPH];   // 8 warp segments of 64 (4KB)
    __shared__ int wcnt[FW];
    __shared__ int offs[FW + 1];
    __shared__ int s_tot;

    const int tid  = threadIdx.x;
    const int wid  = tid >> 5;
    const int blk  = blockIdx.x;
    const int row  = blk >> 1;
    const int half = blk & 1;

    const float4* lg4 = (const float4*)(logits + (size_t)row * QC);
    const int i_base = half * NV4H;

    if (tid < FW) wcnt[tid] = 0;
    __syncthreads();

    int* mycnt = &wcnt[wid];
    unsigned long long* myseg = &seg[wid << 6];
    #define EMIT(val, index) \
        if ((val) > THRESH) { int p = atomicAdd(mycnt, 1); \
            if (p < WSEG) myseg[p] = make_key((val), (index)); }

    const int NFULL = NV4H / (FT * UNROLL);          // 8 full iterations (8192 float4s)
    for (int it = 0; it < NFULL; ++it) {
        const int i0 = i_base + it * FT * UNROLL + tid;
        float4 v[UNROLL];
#pragma unroll
        for (int u = 0; u < UNROLL; ++u) v[u] = lg4[i0 + u * FT];
#pragma unroll
        for (int u = 0; u < UNROLL; ++u) {
            if (max4(v[u]) > THRESH) {
                int base = 4 * (i0 + u * FT);
                EMIT(v[u].x, base + 0); EMIT(v[u].y, base + 1);
                EMIT(v[u].z, base + 2); EMIT(v[u].w, base + 3);
            }
        }
    }
    for (int i = i_base + NFULL * FT * UNROLL + tid; i < i_base + NV4H; i += FT) {
        float4 v = lg4[i];
        if (max4(v) > THRESH) {
            int base = 4 * i;
            EMIT(v.x, base + 0); EMIT(v.y, base + 1);
            EMIT(v.z, base + 2); EMIT(v.w, base + 3);
        }
    }
    #undef EMIT
    __syncthreads();

    // prefix over warp counts; detect segment overflow
    if (tid == 0) {
        int a = 0, bad = 0;
        for (int w = 0; w < FW; ++w) {
            offs[w] = a;
            int c = wcnt[w];
            if (c > WSEG) { bad = 1; c = WSEG; }
            a += c;
        }
        offs[FW] = a;
        s_tot = bad ? -1 : a;
        g_cnt[blk] = s_tot;
    }
    __syncthreads();
    int tot = s_tot;
    if (tot < 0) tot = offs[FW];

    // compact via register staging and dump straight to global, coalesced
    unsigned long long* dst = g_keys + (size_t)blk * CAPH;
    {
        int d0 = tid, d1 = tid + FT;
        if (d0 < tot) {
            int w = 0;
            while (offs[w + 1] <= d0) ++w;
            dst[d0] = seg[(w << 6) + (d0 - offs[w])];
        }
        if (d1 < tot) {
            int w = 0;
            while (offs[w + 1] <= d1) ++w;
            dst[d1] = seg[(w << 6) + (d1 - offs[w])];
        }
    }
}

// ---------------- Kernel 2: rank-by-count selection + gather ----------------
__global__ __launch_bounds__(MT)
void rank_gather_k(const float* __restrict__ logits,
                   const float* __restrict__ boxes,
                   const float* __restrict__ kpts,
                   float* __restrict__ out, int B) {
    __shared__ unsigned long long buf[CAP2];   // [0:cnt) keys; [1024:1324) top region
                                               // fallback: hist[4096] alias + candidates
    __shared__ int qbuf[TOPK];
    __shared__ int s_cnt, s_cut, s_n;

    const int tid = threadIdx.x;
    const int b   = blockIdx.x;

    int cA = g_cnt[2 * b];
    int cB = g_cnt[2 * b + 1];
    int cnt = cA + cB;
    const bool ok = (cA >= 0 && cB >= 0 && cnt >= TOPK && cnt <= 1024);

    int topbase = 1024;   // top region when ok

    if (ok) {
        const unsigned long long* kA = g_keys + (size_t)(2 * b) * CAPH;
        const unsigned long long* kB = g_keys + (size_t)(2 * b + 1) * CAPH;
        for (int i = tid; i < cA; i += MT) buf[i] = kA[i];
        for (int i = tid; i < cB; i += MT) buf[cA + i] = kB[i];
        __syncthreads();

        // rank-by-count: keys unique -> rank is a perfect permutation.
        unsigned long long K0 = (tid < cnt) ? buf[tid] : 0ULL;
        unsigned long long K1 = (tid + MT < cnt) ? buf[tid + MT] : 0ULL;
        int r0 = 0, r1 = 0;
        int j = 0;
        for (; j + 4 <= cnt; j += 4) {
            unsigned long long x0 = buf[j], x1 = buf[j + 1], x2 = buf[j + 2], x3 = buf[j + 3];
            r0 += (x0 > K0) + (x1 > K0) + (x2 > K0) + (x3 > K0);
            r1 += (x0 > K1) + (x1 > K1) + (x2 > K1) + (x3 > K1);
        }
        for (; j < cnt; ++j) {
            unsigned long long x = buf[j];
            r0 += (x > K0);
            r1 += (x > K1);
        }
        __syncthreads();   // all reads of buf[] done before top region written? (top disjoint)
        if (tid < cnt && r0 < TOPK)      buf[topbase + r0] = K0;
        if (tid + MT < cnt && r1 < TOPK) buf[topbase + r1] = K1;
        __syncthreads();
    } else {
        // ---- Fallback (statistically never taken): exact radix-histogram + sort ----
        topbase = 0;
        unsigned int* hist = (unsigned int*)buf;
        for (int i = tid; i < 4096; i += MT) hist[i] = 0u;
        __syncthreads();
        const float* lg = logits + (size_t)b * QC;
        for (int i = tid; i < QC; i += MT) {
            unsigned int u = __float_as_uint(lg[i]);
            u = (u & 0x80000000u) ? ~u : (u | 0x80000000u);
            atomicAdd(&hist[u >> 20], 1u);
        }
        __syncthreads();
        if (tid == 0) {
            int acc = 0, cb = 0;
            for (int bin = 4095; bin >= 0; --bin) {
                acc += (int)hist[bin];
                if (acc >= TOPK) { cb = bin; break; }
            }
            s_cut = cb;
            s_cnt = 0;
        }
        __syncthreads();
        int cut = s_cut;
        for (int i = tid; i < QC; i += MT) {
            float f = lg[i];
            unsigned int u = __float_as_uint(f);
            u = (u & 0x80000000u) ? ~u : (u | 0x80000000u);
            if ((int)(u >> 20) >= cut) {
                int p = atomicAdd(&s_cnt, 1);
                if (p < CAP2) buf[p] = make_key(f, i);
            }
        }
        __syncthreads();
        int c2 = s_cnt;
        if (c2 > CAP2) c2 = CAP2;
        if (tid == 0) {
            int n = 1;
            while (n < c2) n <<= 1;
            s_n = n;
        }
        __syncthreads();
        const int n = s_n;
        for (int i = c2 + tid; i < n; i += MT) buf[i] = 0ULL;
        __syncthreads();
        for (int k = 2; k <= n; k <<= 1) {
            for (int jj = k >> 1; jj > 0; jj >>= 1) {
                for (int i = tid; i < n; i += MT) {
                    int ix = i ^ jj;
                    if (ix > i) {
                        unsigned long long a = buf[i], c = buf[ix];
                        bool desc = ((i & k) == 0);
                        if (desc ? (a < c) : (a > c)) { buf[i] = c; buf[ix] = a; }
                    }
                }
                __syncthreads();
            }
        }
    }

    // ---- emit labels / scores, stash qidx ----
    const size_t L1 = (size_t)B * TOPK;          // boxes offset
    const size_t L2 = L1 + (size_t)B * TOPK * 4; // scores offset
    const size_t L3 = L2 + (size_t)B * TOPK;     // kpts offset

    if (tid < TOPK) {
        unsigned long long key = buf[topbase + tid];
        unsigned int u = (unsigned int)(key >> 32);
        u = (u & 0x80000000u) ? (u & 0x7FFFFFFFu) : ~u;
        float f = __uint_as_float(u);
        int idx = (int)(~(unsigned int)(key & 0xFFFFFFFFu));
        int lab = idx % Cc;
        int q   = idx / Cc;
        qbuf[tid] = q;
        float score = 1.0f / (1.0f + __expf(-f));
        out[(size_t)b * TOPK + tid]      = (float)lab;
        out[L2 + (size_t)b * TOPK + tid] = score;
    }
    __syncthreads();

    // ---- gather boxes (float4) ----
    const float4* bx4 = (const float4*)boxes;
    float4* obx = (float4*)(out + L1);
    if (tid < TOPK) {
        int q = qbuf[tid];
        obx[(size_t)b * TOPK + tid] = bx4[(size_t)b * Bq + q];
    }

    // ---- gather keypoints (float2 per kp) ----
    const float2* kp2 = (const float2*)kpts;
    float2* okp = (float2*)(out + L3);
    for (int i = tid; i < TOPK * KP; i += MT) {
        int t = i / KP;
        int k = i % KP;
        int q = qbuf[t];
        okp[((size_t)b * TOPK + t) * KP + k] = kp2[((size_t)b * Bq + q) * KP + k];
    }
}

extern "C" void kernel_launch(void* const* d_in, const int* in_sizes, int n_in,
                              void* d_out, int out_size) {
    const float* logits = (const float*)d_in[0];   // [B,900,80]
    const float* boxes  = (const float*)d_in[1];   // [B,900,4]
    const float* kpts   = (const float*)d_in[2];   // [B,900,17,2]
    int B = in_sizes[0] / QC;
    filter_k<<<2 * B, FT>>>(logits);
    rank_gather_k<<<B, MT>>>(logits, boxes, kpts, (float*)d_out, B);
}

// round 10
// speedup vs baseline: 1.1902x; 1.1902x over previous
#include <cuda_runtime.h>
#include <cstdint>

#define Bq 900
#define Cc 80
#define QC 72000          // Bq*Cc
#define NV4H 9000         // float4s per half row
#define TOPK 300
#define KP 17
#define THRESH 2.5f
#define MAXB 512

#define FT 256            // k1 threads
#define FW 8              // k1 warps
#define WSEG 64           // keys per warp segment
#define CAPH 512          // per-half capacity (FW*WSEG)
#define UNROLL 6

#define MT 512            // k2 threads
#define CAP2 2048         // k2 shared buffer (16KB); fallback hist alias

// out layout (floats): labels[B*300] | boxes[B*300*4] | scores[B*300] | kpts[B*300*17*2]

__device__ unsigned long long g_keys[(size_t)2 * MAXB * CAPH];  // 4MB, rewritten each run
__device__ int g_cnt[2 * MAXB];                                  // rewritten each run

__device__ __forceinline__ unsigned long long make_key(float f, int idx) {
    unsigned int u = __float_as_uint(f);
    u = (u & 0x80000000u) ? ~u : (u | 0x80000000u);   // monotone-increasing map
    return ((unsigned long long)u << 32) | (unsigned int)(~idx); // smaller idx -> larger key
}

__device__ __forceinline__ float max4(float4 v) {
    return fmaxf(fmaxf(v.x, v.y), fmaxf(v.z, v.w));
}

// ---------------- Kernel 1: stream half-row, filter, coalesced dump (NO sort) ----------------
__global__ __launch_bounds__(FT, 6)
void filter_k(const float* __restrict__ logits) {
    __shared__ unsigned long long seg[CAPH];   // 8 warp segments of 64 (4KB)
    __shared__ int wcnt[FW];
    __shared__ int offs[FW + 1];
    __shared__ int s_tot;

    const int tid  = threadIdx.x;
    const int wid  = tid >> 5;
    const int blk  = blockIdx.x;
    const int row  = blk >> 1;
    const int half = blk & 1;

    const float4* lg4 = (const float4*)(logits + (size_t)row * QC);
    const int i_base = half * NV4H;

    if (tid < FW) wcnt[tid] = 0;
    __syncthreads();

    int* mycnt = &wcnt[wid];
    unsigned long long* myseg = &seg[wid << 6];
    #define EMIT(val, index) \
        if ((val) > THRESH) { int p = atomicAdd(mycnt, 1); \
            if (p < WSEG) myseg[p] = make_key((val), (index)); }

    const int NFULL = NV4H / (FT * UNROLL);          // 5 full iterations (7680 float4s)
    for (int it = 0; it < NFULL; ++it) {
        const int i0 = i_base + it * FT * UNROLL + tid;
        float4 v[UNROLL];
#pragma unroll
        for (int u = 0; u < UNROLL; ++u) v[u] = lg4[i0 + u * FT];
#pragma unroll
        for (int u = 0; u < UNROLL; ++u) {
            if (max4(v[u]) > THRESH) {
                int base = 4 * (i0 + u * FT);
                EMIT(v[u].x, base + 0); EMIT(v[u].y, base + 1);
                EMIT(v[u].z, base + 2); EMIT(v[u].w, base + 3);
            }
        }
    }
    for (int i = i_base + NFULL * FT * UNROLL + tid; i < i_base + NV4H; i += FT) {
        float4 v = lg4[i];
        if (max4(v) > THRESH) {
            int base = 4 * i;
            EMIT(v.x, base + 0); EMIT(v.y, base + 1);
            EMIT(v.z, base + 2); EMIT(v.w, base + 3);
        }
    }
    #undef EMIT
    __syncthreads();

    // prefix over warp counts; detect segment overflow
    if (tid == 0) {
        int a = 0, bad = 0;
        for (int w = 0; w < FW; ++w) {
            offs[w] = a;
            int c = wcnt[w];
            if (c > WSEG) { bad = 1; c = WSEG; }
            a += c;
        }
        offs[FW] = a;
        s_tot = bad ? -1 : a;
        g_cnt[blk] = s_tot;
    }
    __syncthreads();
    int tot = s_tot;
    if (tot < 0) tot = offs[FW];

    // compact via register staging and dump straight to global, coalesced
    unsigned long long* dst = g_keys + (size_t)blk * CAPH;
    {
        int d0 = tid, d1 = tid + FT;
        if (d0 < tot) {
            int w = 0;
            while (offs[w + 1] <= d0) ++w;
            dst[d0] = seg[(w << 6) + (d0 - offs[w])];
        }
        if (d1 < tot) {
            int w = 0;
            while (offs[w + 1] <= d1) ++w;
            dst[d1] = seg[(w << 6) + (d1 - offs[w])];
        }
    }
}

// ---------------- Kernel 2: sort (bitonic) + gather ----------------
__global__ __launch_bounds__(MT)
void sort_gather_k(const float* __restrict__ logits,
                   const float* __restrict__ boxes,
                   const float* __restrict__ kpts,
                   float* __restrict__ out, int B) {
    __shared__ unsigned long long buf[CAP2];   // keys / sort buffer; hist[4096] alias in fallback
    __shared__ int qbuf[TOPK];
    __shared__ int s_cnt, s_cut, s_n;

    const int tid = threadIdx.x;
    const int b   = blockIdx.x;

    int cA = g_cnt[2 * b];
    int cB = g_cnt[2 * b + 1];
    int cnt = cA + cB;
    const bool ok = (cA >= 0 && cB >= 0 && cnt >= TOPK && cnt <= 1024);

    unsigned long long K = 0ULL;

    if (ok && cnt <= MT) {
        // ---- fast path: register bitonic, 1 key/thread, n = 512, descending ----
        const unsigned long long* kA = g_keys + (size_t)(2 * b) * CAPH;
        if (tid < cA)            K = kA[tid];
        else if (tid < cnt)      K = g_keys[(size_t)(2 * b + 1) * CAPH + (tid - cA)];
        for (int k = 2; k <= MT; k <<= 1) {
            bool desc = ((tid & k) == 0);
            for (int j = k >> 1; j > 0; j >>= 1) {
                unsigned long long part;
                if (j >= 32) {
                    __syncthreads();
                    buf[tid] = K;
                    __syncthreads();
                    part = buf[tid ^ j];
                } else {
                    part = __shfl_xor_sync(0xFFFFFFFFu, K, j);
                }
                bool keepMax = (desc == ((tid & j) == 0));
                if (keepMax ? (part > K) : (part < K)) K = part;
            }
        }
        // thread tid holds rank-tid key
    } else {
        if (ok) {
            // mid path: cnt in (512, 1024] -> shared bitonic n=1024
            const unsigned long long* kA = g_keys + (size_t)(2 * b) * CAPH;
            const unsigned long long* kB = g_keys + (size_t)(2 * b + 1) * CAPH;
            for (int i = tid; i < cA; i += MT) buf[i] = kA[i];
            for (int i = tid; i < cB; i += MT) buf[cA + i] = kB[i];
            for (int i = cnt + tid; i < 1024; i += MT) buf[i] = 0ULL;
            __syncthreads();
            if (tid == 0) s_n = 1024;
        } else {
            // ---- Fallback (statistically never taken): exact radix-histogram ----
            unsigned int* hist = (unsigned int*)buf;
            for (int i = tid; i < 4096; i += MT) hist[i] = 0u;
            __syncthreads();
            const float* lg = logits + (size_t)b * QC;
            for (int i = tid; i < QC; i += MT) {
                unsigned int u = __float_as_uint(lg[i]);
                u = (u & 0x80000000u) ? ~u : (u | 0x80000000u);
                atomicAdd(&hist[u >> 20], 1u);
            }
            __syncthreads();
            if (tid == 0) {
                int acc = 0, cb = 0;
                for (int bin = 4095; bin >= 0; --bin) {
                    acc += (int)hist[bin];
                    if (acc >= TOPK) { cb = bin; break; }
                }
                s_cut = cb;
                s_cnt = 0;
            }
            __syncthreads();
            int cut = s_cut;
            for (int i = tid; i < QC; i += MT) {
                float f = lg[i];
                unsigned int u = __float_as_uint(f);
                u = (u & 0x80000000u) ? ~u : (u | 0x80000000u);
                if ((int)(u >> 20) >= cut) {
                    int p = atomicAdd(&s_cnt, 1);
                    if (p < CAP2) buf[p] = make_key(f, i);
                }
            }
            __syncthreads();
            int c2 = s_cnt;
            if (c2 > CAP2) c2 = CAP2;
            if (tid == 0) {
                int n = 1;
                while (n < c2) n <<= 1;
                s_n = n;
            }
            __syncthreads();
            const int n0 = s_n;
            for (int i = c2 + tid; i < n0; i += MT) buf[i] = 0ULL;
            __syncthreads();
        }
        __syncthreads();
        const int n = s_n;
        for (int k = 2; k <= n; k <<= 1) {
            for (int j = k >> 1; j > 0; j >>= 1) {
                for (int i = tid; i < n; i += MT) {
                    int ix = i ^ j;
                    if (ix > i) {
                        unsigned long long a = buf[i], c = buf[ix];
                        bool desc = ((i & k) == 0);
                        if (desc ? (a < c) : (a > c)) { buf[i] = c; buf[ix] = a; }
                    }
                }
                __syncthreads();
            }
        }
        K = buf[tid];
    }

    // ---- emit labels / scores, stash qidx ----
    const size_t L1 = (size_t)B * TOPK;          // boxes offset
    const size_t L2 = L1 + (size_t)B * TOPK * 4; // scores offset
    const size_t L3 = L2 + (size_t)B * TOPK;     // kpts offset

    if (tid < TOPK) {
        unsigned int u = (unsigned int)(K >> 32);
        u = (u & 0x80000000u) ? (u & 0x7FFFFFFFu) : ~u;
        float f = __uint_as_float(u);
        int idx = (int)(~(unsigned int)(K & 0xFFFFFFFFu));
        int lab = idx % Cc;
        int q   = idx / Cc;
        qbuf[tid] = q;
        float score = 1.0f / (1.0f + __expf(-f));
        out[(size_t)b * TOPK + tid]      = (float)lab;
        out[L2 + (size_t)b * TOPK + tid] = score;
    }
    __syncthreads();

    // ---- gather boxes (float4) ----
    const float4* bx4 = (const float4*)boxes;
    float4* obx = (float4*)(out + L1);
    if (tid < TOPK) {
        int q = qbuf[tid];
        obx[(size_t)b * TOPK + tid] = bx4[(size_t)b * Bq + q];
    }

    // ---- gather keypoints (float2 per kp) ----
    const float2* kp2 = (const float2*)kpts;
    float2* okp = (float2*)(out + L3);
    for (int i = tid; i < TOPK * KP; i += MT) {
        int t = i / KP;
        int k = i % KP;
        int q = qbuf[t];
        okp[((size_t)b * TOPK + t) * KP + k] = kp2[((size_t)b * Bq + q) * KP + k];
    }
}

extern "C" void kernel_launch(void* const* d_in, const int* in_sizes, int n_in,
                              void* d_out, int out_size) {
    const float* logits = (const float*)d_in[0];   // [B,900,80]
    const float* boxes  = (const float*)d_in[1];   // [B,900,4]
    const float* kpts   = (const float*)d_in[2];   // [B,900,17,2]
    int B = in_sizes[0] / QC;
    filter_k<<<2 * B, FT>>>(logits);
    sort_gather_k<<<B, MT>>>(logits, boxes, kpts, (float*)d_out, B);
}

// round 13
// speedup vs baseline: 1.4356x; 1.2061x over previous
#include <cuda_runtime.h>
#include <cstdint>

#define Bq 900
#define Cc 80
#define QC 72000          // Bq*Cc
#define NV4H 9000         // float4s per half row
#define TOPK 300
#define KP 17
#define THRESH 2.5f
#define MAXB 512

#define FT 256            // k1 threads
#define FW 8              // k1 warps
#define WSEG 64           // keys per warp segment
#define CAPH 512          // per-half capacity (FW*WSEG)
#define UNROLL 4

#define MT 512            // k2 threads
#define CAP2 2048         // k2 shared buffer (16KB); fallback hist alias

typedef unsigned long long ull;

// out layout (floats): labels[B*300] | boxes[B*300*4] | scores[B*300] | kpts[B*300*17*2]

__device__ ull g_keys[(size_t)2 * MAXB * CAPH];  // 8MB, rewritten each run
__device__ int g_cnt[2 * MAXB];                  // rewritten each run

__device__ __forceinline__ ull make_key(float f, int idx) {
    unsigned int u = __float_as_uint(f);
    u = (u & 0x80000000u) ? ~u : (u | 0x80000000u);   // monotone-increasing map
    return ((ull)u << 32) | (unsigned int)(~idx);     // smaller idx -> larger key
}

__device__ __forceinline__ float max4(float4 v) {
    return fmaxf(fmaxf(v.x, v.y), fmaxf(v.z, v.w));
}

// one bitonic exchange step for element with virtual index i (shfl partner)
__device__ __forceinline__ void bstep(ull& V, int i, int j, int k) {
    ull part = __shfl_xor_sync(0xFFFFFFFFu, V, j);
    bool desc = ((i & k) == 0);
    bool keepMax = (desc == ((i & j) == 0));
    if (keepMax ? (part > V) : (part < V)) V = part;
}

// merge-path round: src runs of length L (descending, duplicate-safe) -> dst runs of 2L
__device__ __forceinline__ void merge_round(const ull* __restrict__ src,
                                            ull* __restrict__ dst, int L, int tid) {
#pragma unroll
    for (int e = 0; e < 2; ++e) {
        int i = tid + e * FT;
        ull x = src[i];
        int o = i & (2 * L - 1);
        int baseL = i - o;
        bool left = (o < L);
        int myoff = left ? o : o - L;
        const ull* part = src + baseL + (left ? L : 0);
        int lo = 0, hi = L;
        if (left) {
            while (lo < hi) { int m = (lo + hi) >> 1; if (part[m] > x) lo = m + 1; else hi = m; }
        } else {
            while (lo < hi) { int m = (lo + hi) >> 1; if (part[m] >= x) lo = m + 1; else hi = m; }
        }
        dst[baseL + myoff + lo] = x;
    }
}

// ---------------- Kernel 1: stream half-row, filter, warp-sort + merge-path, dump sorted ----------------
__global__ __launch_bounds__(FT, 8)
void filter_sort_k(const float* __restrict__ logits) {
    __shared__ ull s0[CAPH];     // warp segments, then ping
    __shared__ ull s1[CAPH];     // pong
    __shared__ int wcnt[FW];

    const int tid  = threadIdx.x;
    const int wid  = tid >> 5;
    const int lane = tid & 31;
    const int blk  = blockIdx.x;
    const int row  = blk >> 1;
    const int half = blk & 1;

    const float4* lg4 = (const float4*)(logits + (size_t)row * QC);
    const int i_base = half * NV4H;

    if (tid < FW) wcnt[tid] = 0;
    __syncthreads();

    int* mycnt = &wcnt[wid];
    ull* myseg = &s0[wid << 6];
    #define EMIT(val, index) \
        if ((val) > THRESH) { int p = atomicAdd(mycnt, 1); \
            if (p < WSEG) myseg[p] = make_key((val), (index)); }

    const int NFULL = NV4H / (FT * UNROLL);          // 8 full iterations (8192 float4s)
    for (int it = 0; it < NFULL; ++it) {
        const int i0 = i_base + it * FT * UNROLL + tid;
        float4 v[UNROLL];
#pragma unroll
        for (int u = 0; u < UNROLL; ++u) v[u] = lg4[i0 + u * FT];
#pragma unroll
        for (int u = 0; u < UNROLL; ++u) {
            if (max4(v[u]) > THRESH) {
                int base = 4 * (i0 + u * FT);
                EMIT(v[u].x, base + 0); EMIT(v[u].y, base + 1);
                EMIT(v[u].z, base + 2); EMIT(v[u].w, base + 3);
            }
        }
    }
    for (int i = i_base + NFULL * FT * UNROLL + tid; i < i_base + NV4H; i += FT) {
        float4 v = lg4[i];
        if (max4(v) > THRESH) {
            int base = 4 * i;
            EMIT(v.x, base + 0); EMIT(v.y, base + 1);
            EMIT(v.z, base + 2); EMIT(v.w, base + 3);
        }
    }
    #undef EMIT
    __syncthreads();

    // total count + overflow flag
    if (tid == 0) {
        int a = 0, bad = 0;
        for (int w = 0; w < FW; ++w) {
            int c = wcnt[w];
            if (c > WSEG) { bad = 1; c = WSEG; }
            a += c;
        }
        g_cnt[blk] = bad ? -1 : a;
    }

    // ---- warp sorts its 64-key segment in registers (shfl only, no barriers) ----
    int c = wcnt[wid];
    if (c > WSEG) c = WSEG;
    ull A = (lane < c) ? myseg[lane] : 0ULL;          // virtual index lane
    ull Bv = (lane + 32 < c) ? myseg[lane + 32] : 0ULL; // virtual index lane+32
    for (int k = 2; k <= 64; k <<= 1) {
        for (int j = k >> 1; j > 0; j >>= 1) {
            if (j == 32) {
                // local exchange between indices lane and lane+32 (desc: A gets max)
                ull mx = (A > Bv) ? A : Bv;
                ull mn = (A > Bv) ? Bv : A;
                A = mx; Bv = mn;
            } else {
                bstep(A, lane, j, k);
                bstep(Bv, lane + 32, j, k);
            }
        }
    }
    myseg[lane] = A;
    myseg[lane + 32] = Bv;
    __syncthreads();

    // ---- 3 merge-path rounds: 8 runs of 64 -> 1 run of 512 (descending) ----
    merge_round(s0, s1, 64, tid);
    __syncthreads();
    merge_round(s1, s0, 128, tid);
    __syncthreads();
    merge_round(s0, s1, 256, tid);
    __syncthreads();

    // coalesced dump of the sorted half
    ull* dst = g_keys + (size_t)blk * CAPH;
    dst[tid] = s1[tid];
    dst[tid + FT] = s1[tid + FT];
}

// ---------------- Kernel 2: merge two sorted halves, gather, write ----------------
__global__ __launch_bounds__(MT)
void merge_gather_k(const float* __restrict__ logits,
                    const float* __restrict__ boxes,
                    const float* __restrict__ kpts,
                    float* __restrict__ out, int B) {
    __shared__ ull buf[CAP2];   // [0:512)=A, [512:1024)=B, [1024:1324) top region
                                // fallback: hist[4096] alias + candidates
    __shared__ int qbuf[TOPK];
    __shared__ int s_cnt, s_cut, s_n;

    const int tid = threadIdx.x;
    const int b   = blockIdx.x;

    int cA = g_cnt[2 * b];
    int cB = g_cnt[2 * b + 1];
    const bool ok = (cA >= 0 && cB >= 0 && cA + cB >= TOPK);

    int topbase = 1024;

    if (ok) {
        buf[tid]       = g_keys[(size_t)(2 * b) * CAPH + tid];      // A sorted desc (zero-pad)
        buf[512 + tid] = g_keys[(size_t)(2 * b + 1) * CAPH + tid];  // B sorted desc (zero-pad)
        __syncthreads();
        // duplicate-stable merge ranks (zeros pad both lists)
        {
            ull x = buf[tid];                 // element of A at index tid
            int lo = 0, hi = 512;
            while (lo < hi) { int m = (lo + hi) >> 1; if (buf[512 + m] > x) lo = m + 1; else hi = m; }
            int r = tid + lo;
            if (r < TOPK) buf[topbase + r] = x;
        }
        {
            ull x = buf[512 + tid];           // element of B at index tid
            int lo = 0, hi = 512;
            while (lo < hi) { int m = (lo + hi) >> 1; if (buf[m] >= x) lo = m + 1; else hi = m; }
            int r = tid + lo;
            if (r < TOPK) buf[topbase + r] = x;
        }
        __syncthreads();
    } else {
        // ---- Fallback (statistically never taken): exact radix-histogram + sort ----
        topbase = 0;
        unsigned int* hist = (unsigned int*)buf;
        for (int i = tid; i < 4096; i += MT) hist[i] = 0u;
        __syncthreads();
        const float* lg = logits + (size_t)b * QC;
        for (int i = tid; i < QC; i += MT) {
            unsigned int u = __float_as_uint(lg[i]);
            u = (u & 0x80000000u) ? ~u : (u | 0x80000000u);
            atomicAdd(&hist[u >> 20], 1u);
        }
        __syncthreads();
        if (tid == 0) {
            int acc = 0, cb = 0;
            for (int bin = 4095; bin >= 0; --bin) {
                acc += (int)hist[bin];
                if (acc >= TOPK) { cb = bin; break; }
            }
            s_cut = cb;
            s_cnt = 0;
        }
        __syncthreads();
        int cut = s_cut;
        for (int i = tid; i < QC; i += MT) {
            float f = lg[i];
            unsigned int u = __float_as_uint(f);
            u = (u & 0x80000000u) ? ~u : (u | 0x80000000u);
            if ((int)(u >> 20) >= cut) {
                int p = atomicAdd(&s_cnt, 1);
                if (p < CAP2) buf[p] = make_key(f, i);
            }
        }
        __syncthreads();
        int c2 = s_cnt;
        if (c2 > CAP2) c2 = CAP2;
        if (tid == 0) {
            int n = 1;
            while (n < c2) n <<= 1;
            s_n = n;
        }
        __syncthreads();
        const int n = s_n;
        for (int i = c2 + tid; i < n; i += MT) buf[i] = 0ULL;
        __syncthreads();
        for (int k = 2; k <= n; k <<= 1) {
            for (int j = k >> 1; j > 0; j >>= 1) {
                for (int i = tid; i < n; i += MT) {
                    int ix = i ^ j;
                    if (ix > i) {
                        ull a = buf[i], c = buf[ix];
                        bool desc = ((i & k) == 0);
                        if (desc ? (a < c) : (a > c)) { buf[i] = c; buf[ix] = a; }
                    }
                }
                __syncthreads();
            }
        }
    }

    // ---- emit labels / scores, stash qidx ----
    const size_t L1 = (size_t)B * TOPK;          // boxes offset
    const size_t L2 = L1 + (size_t)B * TOPK * 4; // scores offset
    const size_t L3 = L2 + (size_t)B * TOPK;     // kpts offset

    if (tid < TOPK) {
        ull key = buf[topbase + tid];
        unsigned int u = (unsigned int)(key >> 32);
        u = (u & 0x80000000u) ? (u & 0x7FFFFFFFu) : ~u;
        float f = __uint_as_float(u);
        int idx = (int)(~(unsigned int)(key & 0xFFFFFFFFu));
        int lab = idx % Cc;
        int q   = idx / Cc;
        qbuf[tid] = q;
        float score = 1.0f / (1.0f + __expf(-f));
        out[(size_t)b * TOPK + tid]      = (float)lab;
        out[L2 + (size_t)b * TOPK + tid] = score;
    }
    __syncthreads();

    // ---- gather boxes (float4) ----
    const float4* bx4 = (const float4*)boxes;
    float4* obx = (float4*)(out + L1);
    if (tid < TOPK) {
        int q = qbuf[tid];
        obx[(size_t)b * TOPK + tid] = bx4[(size_t)b * Bq + q];
    }

    // ---- gather keypoints (float2 per kp) ----
    const float2* kp2 = (const float2*)kpts;
    float2* okp = (float2*)(out + L3);
    for (int i = tid; i < TOPK * KP; i += MT) {
        int t = i / KP;
        int k = i % KP;
        int q = qbuf[t];
        okp[((size_t)b * TOPK + t) * KP + k] = kp2[((size_t)b * Bq + q) * KP + k];
    }
}

extern "C" void kernel_launch(void* const* d_in, const int* in_sizes, int n_in,
                              void* d_out, int out_size) {
    const float* logits = (const float*)d_in[0];   // [B,900,80]
    const float* boxes  = (const float*)d_in[1];   // [B,900,4]
    const float* kpts   = (const float*)d_in[2];   // [B,900,17,2]
    int B = in_sizes[0] / QC;
    filter_sort_k<<<2 * B, FT>>>(logits);
    merge_gather_k<<<B, MT>>>(logits, boxes, kpts, (float*)d_out, B);
}